// round 13
// baseline (speedup 1.0000x reference)
#include <cuda_runtime.h>
#include <math.h>

// Problem-fixed dimensions
#define NNODES 100000
#define NEDGES 1600000
#define CIN 64
#define CH 128
#define GROWS 64         // rows per block in fused agg+GEMM kernels
#define GROWS_F 128      // rows per block in final kernel (512 threads)
#define KFIN 384
#define CSP 132          // padded smem row stride (128+4) -> conflict-free frags

// Scratch (__device__ globals; no allocation allowed)
__device__ __align__(128) float g_bufA[(size_t)NNODES * CH];
__device__ __align__(128) float g_bufB[(size_t)NNODES * CH];
__device__ __align__(128) float g_dinv[NNODES];
__device__ __align__(128) float g_stats[4 * CH];        // [sum1|sq1|sum2|sq2]
__device__ __align__(128) float g_dummy[4 * CH];        // probe stats sink
__device__ __align__(128) int   g_rowptr[NNODES + 1];
__device__ __align__(128) int   g_cursor[NNODES];
__device__ __align__(128) unsigned long long g_csr[NEDGES];  // (norm<<32)|src
__device__ __align__(128) unsigned g_Wtc1[CIN * CH];    // tf32 B-frag packed W1
__device__ __align__(128) unsigned g_Wtc2[CH * CH];     // tf32 B-frag packed W2
__device__ __align__(128) unsigned g_Wtcm[KFIN * CH];   // tf32 B-frag packed Wm
__device__ __align__(128) int   g_part[256];            // scan partials
__device__ int g_idx32;

#define SCAN_BLOCKS 196
#define SCAN_BT 512

// ---------------------------------------------------------------------------
typedef unsigned long long ull;

__device__ __forceinline__ void csr_get(ull e, int& src, float& norm) {
    src = (int)(unsigned)(e & 0xFFFFFFFFull);
    norm = __uint_as_float((unsigned)(e >> 32));
}
__device__ __forceinline__ unsigned cvt_tf32(float f) {
    unsigned u;
    asm("cvt.rna.tf32.f32 %0, %1;" : "=r"(u) : "f"(f));
    return u;
}
__device__ __forceinline__ void mma_tf32(float* d, unsigned a0, unsigned a1,
                                         unsigned a2, unsigned a3,
                                         unsigned b0, unsigned b1) {
    asm("mma.sync.aligned.m16n8k8.row.col.f32.tf32.tf32.f32 "
        "{%0,%1,%2,%3},{%4,%5,%6,%7},{%8,%9},{%0,%1,%2,%3};"
        : "+f"(d[0]), "+f"(d[1]), "+f"(d[2]), "+f"(d[3])
        : "r"(a0), "r"(a1), "r"(a2), "r"(a3), "r"(b0), "r"(b1));
}

// Accumulate one gathered row into acc (BN+ReLU applied when BN).
template <bool BN>
__device__ __forceinline__ void acc_edge(float4& acc, float4 v, float n,
                                         const float4& scv, const float4& shv) {
    if (BN) {
        acc.x += n * fmaxf(v.x * scv.x + shv.x, 0.0f);
        acc.y += n * fmaxf(v.y * scv.y + shv.y, 0.0f);
        acc.z += n * fmaxf(v.z * scv.z + shv.z, 0.0f);
        acc.w += n * fmaxf(v.w * scv.w + shv.w, 0.0f);
    } else {
        acc.x += n * v.x;
        acc.y += n * v.y;
        acc.z += n * v.z;
        acc.w += n * v.w;
    }
}

// ---------------------------------------------------------------------------
__global__ void detect_idx_kernel(const int* __restrict__ ei) {
    __shared__ int s_any;
    if (threadIdx.x == 0) s_any = 0;
    __syncthreads();
    int any = 0;
    for (int i = 1 + 2 * threadIdx.x; i < 4096; i += 2 * blockDim.x) any |= ei[i];
    if (any) atomicOr(&s_any, 1);
    __syncthreads();
    if (threadIdx.x == 0) g_idx32 = (s_any != 0) ? 1 : 0;
}

__device__ __forceinline__ void load_edge(const void* ei, int e, int& src, int& dst) {
    if (g_idx32) {
        const int* p = (const int*)ei;
        src = p[e];
        dst = p[NEDGES + e];
    } else {
        const long long* p = (const long long*)ei;
        src = (int)p[e];
        dst = (int)p[NEDGES + e];
    }
}

__global__ void deg_init_kernel() {
    int i = blockIdx.x * blockDim.x + threadIdx.x;
    if (i < NNODES) {
        g_dinv[i] = 1.0f;
        g_cursor[i] = 0;
    }
    if (i < 4 * CH) g_stats[i] = 0.0f;
}

__global__ void deg_count_kernel(const void* __restrict__ ei,
                                 const float* __restrict__ ew) {
    int e = blockIdx.x * blockDim.x + threadIdx.x;
    if (e >= NEDGES) return;
    int dst;
    if (g_idx32) dst = ((const int*)ei)[NEDGES + e];
    else         dst = (int)((const long long*)ei)[NEDGES + e];
    atomicAdd(&g_dinv[dst], ew[e]);
    atomicAdd(&g_cursor[dst], 1);
}

// ---------------------------------------------------------------------------
// 3-phase multi-block scan of counts -> rowptr/cursor; also dinv = rsqrt(deg).
// ---------------------------------------------------------------------------
__global__ __launch_bounds__(SCAN_BT) void scanA_kernel() {
    __shared__ int ssum[SCAN_BT];
    int i = blockIdx.x * SCAN_BT + threadIdx.x;
    int c = (i < NNODES) ? g_cursor[i] : 0;
    if (i < NNODES) g_dinv[i] = rsqrtf(g_dinv[i]);
    ssum[threadIdx.x] = c;
    __syncthreads();
    for (int off = 1; off < SCAN_BT; off <<= 1) {
        int v = (threadIdx.x >= off) ? ssum[threadIdx.x - off] : 0;
        __syncthreads();
        ssum[threadIdx.x] += v;
        __syncthreads();
    }
    if (i < NNODES) g_rowptr[i] = ssum[threadIdx.x];
    if (threadIdx.x == SCAN_BT - 1) g_part[blockIdx.x] = ssum[threadIdx.x];
}

__global__ __launch_bounds__(256) void scanB_kernel() {
    __shared__ int ssum[256];
    int t = threadIdx.x;
    ssum[t] = (t < SCAN_BLOCKS) ? g_part[t] : 0;
    __syncthreads();
    for (int off = 1; off < 256; off <<= 1) {
        int v = (t >= off) ? ssum[t - off] : 0;
        __syncthreads();
        ssum[t] += v;
        __syncthreads();
    }
    g_part[t] = (t == 0) ? 0 : ssum[t - 1];
    if (t == 255) g_rowptr[NNODES] = ssum[255];
}

__global__ __launch_bounds__(SCAN_BT) void scanC_kernel() {
    int i = blockIdx.x * SCAN_BT + threadIdx.x;
    if (i >= NNODES) return;
    int off = g_part[blockIdx.x];
    int excl = g_rowptr[i] + off - g_cursor[i];
    g_rowptr[i] = excl;
    g_cursor[i] = excl;
}

__global__ void fill_kernel(const void* __restrict__ ei,
                            const float* __restrict__ ew) {
    int e = blockIdx.x * blockDim.x + threadIdx.x;
    if (e >= NEDGES) return;
    int src, dst;
    load_edge(ei, e, src, dst);
    float norm = g_dinv[src] * ew[e] * g_dinv[dst];
    int pos = atomicAdd(&g_cursor[dst], 1);
    g_csr[pos] = ((ull)__float_as_uint(norm) << 32) | (unsigned)src;
}

// ---------------------------------------------------------------------------
// Pack weight matrices into tf32 B-fragment lane order.
// ---------------------------------------------------------------------------
__device__ __forceinline__ void pack_one(const float* W, unsigned* Wtc, int i) {
    int tile = i >> 6;              // kt*16 + nt
    int within = i & 63;
    int t = within >> 1;
    int e = within & 1;
    int kt = tile >> 4;
    int nt = tile & 15;
    int k = kt * 8 + (t & 3) + e * 4;
    int n = nt * 8 + (t >> 2);
    Wtc[i] = cvt_tf32(W[k * CH + n]);
}

__global__ void pack_kernel(const float* __restrict__ W1,
                            const float* __restrict__ W2,
                            const float* __restrict__ Wm) {
    const int n1 = CIN * CH;
    const int n2 = CH * CH;
    const int n3 = KFIN * CH;
    for (int idx = blockIdx.x * blockDim.x + threadIdx.x; idx < n1 + n2 + n3;
         idx += gridDim.x * blockDim.x) {
        int i = idx;
        if (i < n1)           pack_one(W1, g_Wtc1, i);
        else if (i < n1 + n2) pack_one(W2, g_Wtc2, i - n1);
        else                  pack_one(Wm, g_Wtcm, i - n1 - n2);
    }
}

// ---------------------------------------------------------------------------
// Fused aggregate + TF32 GEMM. 8-wide unrolled gather for MLP.
// ---------------------------------------------------------------------------
template <int K, bool BN>
__global__ __launch_bounds__(256) void agg_gemm_tc_kernel(
        const float* __restrict__ H,            // gather source [N,K]
        const unsigned* __restrict__ Wtc,
        const float* __restrict__ b,
        const float* __restrict__ gamma,
        const float* __restrict__ beta,
        const float* __restrict__ statsIn,
        float* __restrict__ C,
        float* __restrict__ statsOut) {
    constexpr int KP = K + 4;
    __shared__ float xs[GROWS * KP];
    __shared__ float sc[CH], sh[CH];
    const int row0 = blockIdx.x * GROWS;
    const int tid = threadIdx.x;
    const int warp = tid >> 5;
    const int lane = tid & 31;

    if (BN) {
        if (tid < CH) {
            float mean = statsIn[tid] * (1.0f / NNODES);
            float var = statsIn[CH + tid] * (1.0f / NNODES) - mean * mean;
            float scale = gamma[tid] * rsqrtf(var + 1e-5f);
            sc[tid] = scale;
            sh[tid] = beta[tid] - mean * scale;
        }
        __syncthreads();
    }

    // ---------------- Phase 1: gather-aggregate into xs ----------------
    const int RPW = (K == 128) ? 1 : 2;      // nodes handled per warp-iteration
    const int l16 = (K == 128) ? lane : (lane & 15);
    const int half = (K == 128) ? 0 : (lane >> 4);
    const int NV = K / 4 / ((K == 128) ? 1 : 1);  // float4s per row per node-group
    (void)NV;
    const float4* h4 = (const float4*)H;
    const int rowlen = K / 4;                 // float4 per row (16 or 32)
    float4 scv = make_float4(0, 0, 0, 0), shv = scv;
    if (BN) {
        scv = *(const float4*)&sc[l16 * 4];
        shv = *(const float4*)&sh[l16 * 4];
    }

#pragma unroll 1
    for (int i = 0; i < 8 / RPW; i++) {
        int node = min(row0 + warp * 8 + RPW * i + half, NNODES - 1);
        float di = g_dinv[node];
        float s = di * di;
        float4 hv = h4[(size_t)node * rowlen + l16];
        float4 acc;
        if (BN) {
            acc.x = s * fmaxf(hv.x * scv.x + shv.x, 0.0f);
            acc.y = s * fmaxf(hv.y * scv.y + shv.y, 0.0f);
            acc.z = s * fmaxf(hv.z * scv.z + shv.z, 0.0f);
            acc.w = s * fmaxf(hv.w * scv.w + shv.w, 0.0f);
        } else {
            acc = make_float4(s * hv.x, s * hv.y, s * hv.z, s * hv.w);
        }
        int j = g_rowptr[node];
        int end = g_rowptr[node + 1];
        // 8-wide: 8 independent gathers in flight
        for (; j + 7 < end; j += 8) {
            int si[8];
            float ni[8];
            float4 vi[8];
#pragma unroll
            for (int u = 0; u < 8; u++) csr_get(g_csr[j + u], si[u], ni[u]);
#pragma unroll
            for (int u = 0; u < 8; u++) vi[u] = h4[(size_t)si[u] * rowlen + l16];
#pragma unroll
            for (int u = 0; u < 8; u++) acc_edge<BN>(acc, vi[u], ni[u], scv, shv);
        }
        for (; j + 3 < end; j += 4) {
            int si[4];
            float ni[4];
            float4 vi[4];
#pragma unroll
            for (int u = 0; u < 4; u++) csr_get(g_csr[j + u], si[u], ni[u]);
#pragma unroll
            for (int u = 0; u < 4; u++) vi[u] = h4[(size_t)si[u] * rowlen + l16];
#pragma unroll
            for (int u = 0; u < 4; u++) acc_edge<BN>(acc, vi[u], ni[u], scv, shv);
        }
        for (; j < end; j++) {
            int s0;
            float n0;
            csr_get(g_csr[j], s0, n0);
            acc_edge<BN>(acc, h4[(size_t)s0 * rowlen + l16], n0, scv, shv);
        }
        *(float4*)&xs[(warp * 8 + RPW * i + half) * KP + l16 * 4] = acc;
    }
    __syncthreads();

    // ---------------- Phase 2: TF32 MMA ----------------
    const int rg = warp >> 1;
    const int chf = warp & 1;
    const int r0 = lane >> 2;
    const int c0 = lane & 3;

    float acc[8][4];
#pragma unroll
    for (int nt = 0; nt < 8; nt++)
#pragma unroll
        for (int i = 0; i < 4; i++) acc[nt][i] = 0.0f;

    const float* a_lo = &xs[(16 * rg + r0) * KP];
    const float* a_hi = a_lo + 8 * KP;

#pragma unroll
    for (int kt = 0; kt < K / 8; kt++) {
        int col = kt * 8 + c0;
        unsigned a0 = cvt_tf32(a_lo[col]);
        unsigned a1 = cvt_tf32(a_hi[col]);
        unsigned a2 = cvt_tf32(a_lo[col + 4]);
        unsigned a3 = cvt_tf32(a_hi[col + 4]);
        const uint2* wrow = (const uint2*)(Wtc + (size_t)(kt * 16 + chf * 8) * 64) + lane;
#pragma unroll
        for (int nt = 0; nt < 8; nt++) {
            uint2 bw = wrow[nt * 32];
            mma_tf32(acc[nt], a0, a1, a2, a3, bw.x, bw.y);
        }
    }

    const int ra = row0 + 16 * rg + r0;
    const int rb = ra + 8;
    const bool va = ra < NNODES, vb = rb < NNODES;
#pragma unroll
    for (int nt = 0; nt < 8; nt++) {
        int c = chf * 64 + nt * 8 + c0 * 2;
        float b0 = b[c], b1 = b[c + 1];
        float v00 = acc[nt][0] + b0, v01 = acc[nt][1] + b1;
        float v10 = acc[nt][2] + b0, v11 = acc[nt][3] + b1;
        if (va) {
            C[(size_t)ra * CH + c] = v00;
            C[(size_t)ra * CH + c + 1] = v01;
        }
        if (vb) {
            C[(size_t)rb * CH + c] = v10;
            C[(size_t)rb * CH + c + 1] = v11;
        }
        float s0 = (va ? v00 : 0.0f) + (vb ? v10 : 0.0f);
        float q0 = (va ? v00 * v00 : 0.0f) + (vb ? v10 * v10 : 0.0f);
        float s1 = (va ? v01 : 0.0f) + (vb ? v11 : 0.0f);
        float q1 = (va ? v01 * v01 : 0.0f) + (vb ? v11 * v11 : 0.0f);
#pragma unroll
        for (int m = 16; m >= 4; m >>= 1) {
            s0 += __shfl_xor_sync(0xFFFFFFFF, s0, m);
            q0 += __shfl_xor_sync(0xFFFFFFFF, q0, m);
            s1 += __shfl_xor_sync(0xFFFFFFFF, s1, m);
            q1 += __shfl_xor_sync(0xFFFFFFFF, q1, m);
        }
        if (r0 == 0) {
            atomicAdd(&statsOut[c], s0);
            atomicAdd(&statsOut[CH + c], q0);
            atomicAdd(&statsOut[c + 1], s1);
            atomicAdd(&statsOut[CH + c + 1], q1);
        }
    }
}

// ---------------------------------------------------------------------------
// Final fused layer, TF32 TC, 512 threads, 128 rows/block (dynamic smem).
// ---------------------------------------------------------------------------
__global__ __launch_bounds__(512) void final_tc_kernel(const float* __restrict__ h,
                                                       const float* __restrict__ dist,
                                                       const float* __restrict__ degf,
                                                       const float* __restrict__ Wd,
                                                       const float* __restrict__ bd,
                                                       const float* __restrict__ Wg,
                                                       const float* __restrict__ bg,
                                                       const unsigned* __restrict__ Wtc,
                                                       const float* __restrict__ bm,
                                                       const float* __restrict__ gamma,
                                                       const float* __restrict__ beta,
                                                       float* __restrict__ out) {
    extern __shared__ float smem[];
    float* cs = smem;                       // [GROWS_F][CSP]
    float* sc = smem + GROWS_F * CSP;
    float* sh = sc + CH;
    float* swd = sh + CH;
    float* sbd = swd + CH;
    float* swg = sbd + CH;
    float* sbg = swg + CH;
    const int row0 = blockIdx.x * GROWS_F;
    const int tid = threadIdx.x;

    if (tid < CH) {
        float mean = g_stats[2 * CH + tid] * (1.0f / NNODES);
        float var = g_stats[3 * CH + tid] * (1.0f / NNODES) - mean * mean;
        float scale = gamma[tid] * rsqrtf(var + 1e-5f);
        sc[tid] = scale;
        sh[tid] = beta[tid] - mean * scale;
        swd[tid] = Wd[tid];
        sbd[tid] = bd[tid];
        swg[tid] = Wg[tid];
        sbg[tid] = bg[tid];
    }
    __syncthreads();

    const float4* h4 = (const float4*)h;
#pragma unroll 1
    for (int i = tid; i < GROWS_F * CH / 4; i += 512) {
        int r = i >> 5;
        int cc = (i & 31) * 4;
        int row = min(row0 + r, NNODES - 1);
        float4 v = h4[(size_t)row * 32 + (i & 31)];
        float4 scv = *(const float4*)&sc[cc];
        float4 shv = *(const float4*)&sh[cc];
        v.x = fmaxf(v.x * scv.x + shv.x, 0.0f);
        v.y = fmaxf(v.y * scv.y + shv.y, 0.0f);
        v.z = fmaxf(v.z * scv.z + shv.z, 0.0f);
        v.w = fmaxf(v.w * scv.w + shv.w, 0.0f);
        *(float4*)&cs[r * CSP + cc] = v;
    }
    __syncthreads();

    const int warp = tid >> 5;
    const int lane = tid & 31;
    const int rg = warp >> 1;
    const int chf = warp & 1;
    const int r0 = lane >> 2;
    const int c0 = lane & 3;

    const int ra = row0 + 16 * rg + r0;
    const int rb = ra + 8;
    const float dra = dist[min(ra, NNODES - 1)];
    const float drb = dist[min(rb, NNODES - 1)];
    const float gra = degf[min(ra, NNODES - 1)];
    const float grb = degf[min(rb, NNODES - 1)];

    float acc[8][4];
#pragma unroll
    for (int nt = 0; nt < 8; nt++)
#pragma unroll
        for (int i = 0; i < 4; i++) acc[nt][i] = 0.0f;

    const float* a_lo = &cs[(16 * rg + r0) * CSP];
    const float* a_hi = a_lo + 8 * CSP;

#pragma unroll
    for (int kt = 0; kt < 16; kt++) {
        int col = kt * 8 + c0;
        unsigned a0 = cvt_tf32(a_lo[col]);
        unsigned a1 = cvt_tf32(a_hi[col]);
        unsigned a2 = cvt_tf32(a_lo[col + 4]);
        unsigned a3 = cvt_tf32(a_hi[col + 4]);
        const uint2* wrow = (const uint2*)(Wtc + (size_t)(kt * 16 + chf * 8) * 64) + lane;
#pragma unroll
        for (int nt = 0; nt < 8; nt++) {
            uint2 bw = wrow[nt * 32];
            mma_tf32(acc[nt], a0, a1, a2, a3, bw.x, bw.y);
        }
    }
#pragma unroll
    for (int kt = 16; kt < 32; kt++) {
        int kk = (kt - 16) * 8 + c0;
        unsigned a0 = cvt_tf32(fmaxf(dra * swd[kk] + sbd[kk], 0.0f));
        unsigned a1 = cvt_tf32(fmaxf(drb * swd[kk] + sbd[kk], 0.0f));
        unsigned a2 = cvt_tf32(fmaxf(dra * swd[kk + 4] + sbd[kk + 4], 0.0f));
        unsigned a3 = cvt_tf32(fmaxf(drb * swd[kk + 4] + sbd[kk + 4], 0.0f));
        const uint2* wrow = (const uint2*)(Wtc + (size_t)(kt * 16 + chf * 8) * 64) + lane;
#pragma unroll
        for (int nt = 0; nt < 8; nt++) {
            uint2 bw = wrow[nt * 32];
            mma_tf32(acc[nt], a0, a1, a2, a3, bw.x, bw.y);
        }
    }
#pragma unroll
    for (int kt = 32; kt < 48; kt++) {
        int kk = (kt - 32) * 8 + c0;
        unsigned a0 = cvt_tf32(fmaxf(gra * swg[kk] + sbg[kk], 0.0f));
        unsigned a1 = cvt_tf32(fmaxf(grb * swg[kk] + sbg[kk], 0.0f));
        unsigned a2 = cvt_tf32(fmaxf(gra * swg[kk + 4] + sbg[kk + 4], 0.0f));
        unsigned a3 = cvt_tf32(fmaxf(grb * swg[kk + 4] + sbg[kk + 4], 0.0f));
        const uint2* wrow = (const uint2*)(Wtc + (size_t)(kt * 16 + chf * 8) * 64) + lane;
#pragma unroll
        for (int nt = 0; nt < 8; nt++) {
            uint2 bw = wrow[nt * 32];
            mma_tf32(acc[nt], a0, a1, a2, a3, bw.x, bw.y);
        }
    }

#pragma unroll
    for (int nt = 0; nt < 8; nt++) {
        int c = chf * 64 + nt * 8 + c0 * 2;
        float bm0 = bm[c], bm1 = bm[c + 1];
        if (ra < NNODES) {
            out[(size_t)ra * CH + c] = acc[nt][0] + bm0;
            out[(size_t)ra * CH + c + 1] = acc[nt][1] + bm1;
        }
        if (rb < NNODES) {
            out[(size_t)rb * CH + c] = acc[nt][2] + bm0;
            out[(size_t)rb * CH + c + 1] = acc[nt][3] + bm1;
        }
    }
}

// ---------------------------------------------------------------------------
extern "C" void kernel_launch(void* const* d_in, const int* in_sizes, int n_in,
                              void* d_out, int out_size) {
    const float* x     = (const float*)d_in[0];
    const void*  ei    = d_in[1];
    const float* ew    = (const float*)d_in[2];
    const float* dist  = (const float*)d_in[3];
    const float* degf  = (const float*)d_in[4];
    const float* W1    = (const float*)d_in[5];
    const float* b1    = (const float*)d_in[6];
    const float* W2    = (const float*)d_in[7];
    const float* b2    = (const float*)d_in[8];
    const float* g1    = (const float*)d_in[9];
    const float* be1   = (const float*)d_in[10];
    const float* g2    = (const float*)d_in[11];
    const float* be2   = (const float*)d_in[12];
    const float* Wd    = (const float*)d_in[13];
    const float* bd    = (const float*)d_in[14];
    const float* Wg    = (const float*)d_in[15];
    const float* bg    = (const float*)d_in[16];
    const float* Wm    = (const float*)d_in[17];
    const float* bm    = (const float*)d_in[18];
    float* out = (float*)d_out;

    float *bufA, *bufB, *stats, *dummy;
    unsigned *Wtc1, *Wtc2, *Wtcm;
    cudaGetSymbolAddress((void**)&bufA, g_bufA);
    cudaGetSymbolAddress((void**)&bufB, g_bufB);
    cudaGetSymbolAddress((void**)&stats, g_stats);
    cudaGetSymbolAddress((void**)&dummy, g_dummy);
    cudaGetSymbolAddress((void**)&Wtc1, g_Wtc1);
    cudaGetSymbolAddress((void**)&Wtc2, g_Wtc2);
    cudaGetSymbolAddress((void**)&Wtcm, g_Wtcm);

    const int nodeBlocks = (NNODES + 255) / 256;
    const int edgeBlocks = (NEDGES + 255) / 256;
    const int gemmBlocks = (NNODES + GROWS - 1) / GROWS;       // 1563
    const int finBlocks  = (NNODES + GROWS_F - 1) / GROWS_F;   // 782
    const int FIN_SMEM = (GROWS_F * CSP + 6 * CH) * 4;         // 70656 B

    cudaFuncSetAttribute(final_tc_kernel, cudaFuncAttributeMaxDynamicSharedMemorySize, FIN_SMEM);

    // slots 0-2
    detect_idx_kernel<<<1, 256>>>((const int*)ei);
    deg_init_kernel<<<nodeBlocks, 256>>>();
    pack_kernel<<<160, 256>>>(W1, W2, Wm);

    // slot 3: ncu PROBE of fused agg+gemm layer 2 (dummy stats sink;
    // bufA/stats state it touches is fully rebuilt by the real kernels below)
    agg_gemm_tc_kernel<CH, true><<<296, 256>>>(
        bufB, Wtc2, b2, g1, be1, stats, bufA, dummy);

    // --- gcn_norm + CSR build ---
    deg_count_kernel<<<edgeBlocks, 256>>>(ei, ew);
    scanA_kernel<<<SCAN_BLOCKS, SCAN_BT>>>();
    scanB_kernel<<<1, 256>>>();
    scanC_kernel<<<SCAN_BLOCKS, SCAN_BT>>>();
    fill_kernel<<<edgeBlocks, 256>>>(ei, ew);

    // --- layer 1: fused aggregate(x) + GEMM (stats1) ---
    agg_gemm_tc_kernel<CIN, false><<<gemmBlocks, 256>>>(
        x, Wtc1, b1, nullptr, nullptr, nullptr, bufB, stats);

    // --- layer 2: fused aggregate(bn1(h1)) + GEMM (stats2) ---
    agg_gemm_tc_kernel<CH, true><<<gemmBlocks, 256>>>(
        bufB, Wtc2, b2, g1, be1, stats, bufA, stats + 2 * CH);

    // --- final (TF32 TC, 512 threads, 128 rows/block) ---
    final_tc_kernel<<<finBlocks, 512, FIN_SMEM>>>(bufA, dist, degf, Wd, bd, Wg, bg,
                                                  Wtcm, bm, g2, be2, out);
}

// round 14
// speedup vs baseline: 1.1852x; 1.1852x over previous
#include <cuda_runtime.h>
#include <math.h>

// Problem-fixed dimensions
#define NNODES 100000
#define NEDGES 1600000
#define CIN 64
#define CH 128
#define GROWS 32         // rows per block in fused agg+GEMM kernels
#define GROWS_F 128      // rows per block in final kernel (512 threads)
#define KFIN 384
#define CSP 132          // padded smem row stride (128+4) -> conflict-free frags

// Scratch (__device__ globals; no allocation allowed)
__device__ __align__(128) float g_bufA[(size_t)NNODES * CH];
__device__ __align__(128) float g_bufB[(size_t)NNODES * CH];
__device__ __align__(128) float g_dinv[NNODES];
__device__ __align__(128) float g_stats[4 * CH];        // [sum1|sq1|sum2|sq2]
__device__ __align__(128) int   g_rowptr[NNODES + 1];
__device__ __align__(128) int   g_cursor[NNODES];
__device__ __align__(128) unsigned long long g_csr[NEDGES];  // (norm<<32)|src
__device__ __align__(128) unsigned g_Wtc1[CIN * CH];    // tf32 B-frag packed W1
__device__ __align__(128) unsigned g_Wtc2[CH * CH];     // tf32 B-frag packed W2
__device__ __align__(128) unsigned g_Wtcm[KFIN * CH];   // tf32 B-frag packed Wm
__device__ __align__(128) int   g_part[256];            // scan partials
__device__ int g_idx32;

#define SCAN_BLOCKS 196
#define SCAN_BT 512

// ---------------------------------------------------------------------------
typedef unsigned long long ull;

__device__ __forceinline__ void csr_get(ull e, int& src, float& norm) {
    src = (int)(unsigned)(e & 0xFFFFFFFFull);
    norm = __uint_as_float((unsigned)(e >> 32));
}
__device__ __forceinline__ unsigned cvt_tf32(float f) {
    unsigned u;
    asm("cvt.rna.tf32.f32 %0, %1;" : "=r"(u) : "f"(f));
    return u;
}
__device__ __forceinline__ void mma_tf32(float* d, unsigned a0, unsigned a1,
                                         unsigned a2, unsigned a3,
                                         unsigned b0, unsigned b1) {
    asm("mma.sync.aligned.m16n8k8.row.col.f32.tf32.tf32.f32 "
        "{%0,%1,%2,%3},{%4,%5,%6,%7},{%8,%9},{%0,%1,%2,%3};"
        : "+f"(d[0]), "+f"(d[1]), "+f"(d[2]), "+f"(d[3])
        : "r"(a0), "r"(a1), "r"(a2), "r"(a3), "r"(b0), "r"(b1));
}

template <bool BN>
__device__ __forceinline__ void acc_edge(float4& acc, float4 v, float n,
                                         const float4& scv, const float4& shv) {
    if (BN) {
        acc.x += n * fmaxf(v.x * scv.x + shv.x, 0.0f);
        acc.y += n * fmaxf(v.y * scv.y + shv.y, 0.0f);
        acc.z += n * fmaxf(v.z * scv.z + shv.z, 0.0f);
        acc.w += n * fmaxf(v.w * scv.w + shv.w, 0.0f);
    } else {
        acc.x += n * v.x;
        acc.y += n * v.y;
        acc.z += n * v.z;
        acc.w += n * v.w;
    }
}

// ---------------------------------------------------------------------------
__global__ void detect_idx_kernel(const int* __restrict__ ei) {
    __shared__ int s_any;
    if (threadIdx.x == 0) s_any = 0;
    __syncthreads();
    int any = 0;
    for (int i = 1 + 2 * threadIdx.x; i < 4096; i += 2 * blockDim.x) any |= ei[i];
    if (any) atomicOr(&s_any, 1);
    __syncthreads();
    if (threadIdx.x == 0) g_idx32 = (s_any != 0) ? 1 : 0;
}

__device__ __forceinline__ void load_edge(const void* ei, int e, int& src, int& dst) {
    if (g_idx32) {
        const int* p = (const int*)ei;
        src = p[e];
        dst = p[NEDGES + e];
    } else {
        const long long* p = (const long long*)ei;
        src = (int)p[e];
        dst = (int)p[NEDGES + e];
    }
}

__global__ void deg_init_kernel() {
    int i = blockIdx.x * blockDim.x + threadIdx.x;
    if (i < NNODES) {
        g_dinv[i] = 1.0f;
        g_cursor[i] = 0;
    }
    if (i < 4 * CH) g_stats[i] = 0.0f;
}

__global__ void deg_count_kernel(const void* __restrict__ ei,
                                 const float* __restrict__ ew) {
    int e = blockIdx.x * blockDim.x + threadIdx.x;
    if (e >= NEDGES) return;
    int dst;
    if (g_idx32) dst = ((const int*)ei)[NEDGES + e];
    else         dst = (int)((const long long*)ei)[NEDGES + e];
    atomicAdd(&g_dinv[dst], ew[e]);
    atomicAdd(&g_cursor[dst], 1);
}

// ---------------------------------------------------------------------------
// 3-phase multi-block scan of counts -> rowptr/cursor; also dinv = rsqrt(deg).
// ---------------------------------------------------------------------------
__global__ __launch_bounds__(SCAN_BT) void scanA_kernel() {
    __shared__ int ssum[SCAN_BT];
    int i = blockIdx.x * SCAN_BT + threadIdx.x;
    int c = (i < NNODES) ? g_cursor[i] : 0;
    if (i < NNODES) g_dinv[i] = rsqrtf(g_dinv[i]);
    ssum[threadIdx.x] = c;
    __syncthreads();
    for (int off = 1; off < SCAN_BT; off <<= 1) {
        int v = (threadIdx.x >= off) ? ssum[threadIdx.x - off] : 0;
        __syncthreads();
        ssum[threadIdx.x] += v;
        __syncthreads();
    }
    if (i < NNODES) g_rowptr[i] = ssum[threadIdx.x];
    if (threadIdx.x == SCAN_BT - 1) g_part[blockIdx.x] = ssum[threadIdx.x];
}

__global__ __launch_bounds__(256) void scanB_kernel() {
    __shared__ int ssum[256];
    int t = threadIdx.x;
    ssum[t] = (t < SCAN_BLOCKS) ? g_part[t] : 0;
    __syncthreads();
    for (int off = 1; off < 256; off <<= 1) {
        int v = (t >= off) ? ssum[t - off] : 0;
        __syncthreads();
        ssum[t] += v;
        __syncthreads();
    }
    g_part[t] = (t == 0) ? 0 : ssum[t - 1];
    if (t == 255) g_rowptr[NNODES] = ssum[255];
}

__global__ __launch_bounds__(SCAN_BT) void scanC_kernel() {
    int i = blockIdx.x * SCAN_BT + threadIdx.x;
    if (i >= NNODES) return;
    int off = g_part[blockIdx.x];
    int excl = g_rowptr[i] + off - g_cursor[i];
    g_rowptr[i] = excl;
    g_cursor[i] = excl;
}

__global__ void fill_kernel(const void* __restrict__ ei,
                            const float* __restrict__ ew) {
    int e = blockIdx.x * blockDim.x + threadIdx.x;
    if (e >= NEDGES) return;
    int src, dst;
    load_edge(ei, e, src, dst);
    float norm = g_dinv[src] * ew[e] * g_dinv[dst];
    int pos = atomicAdd(&g_cursor[dst], 1);
    g_csr[pos] = ((ull)__float_as_uint(norm) << 32) | (unsigned)src;
}

// ---------------------------------------------------------------------------
// Pack weight matrices into tf32 B-fragment lane order.
// ---------------------------------------------------------------------------
__device__ __forceinline__ void pack_one(const float* W, unsigned* Wtc, int i) {
    int tile = i >> 6;              // kt*16 + nt
    int within = i & 63;
    int t = within >> 1;
    int e = within & 1;
    int kt = tile >> 4;
    int nt = tile & 15;
    int k = kt * 8 + (t & 3) + e * 4;
    int n = nt * 8 + (t >> 2);
    Wtc[i] = cvt_tf32(W[k * CH + n]);
}

__global__ void pack_kernel(const float* __restrict__ W1,
                            const float* __restrict__ W2,
                            const float* __restrict__ Wm) {
    const int n1 = CIN * CH;
    const int n2 = CH * CH;
    const int n3 = KFIN * CH;
    for (int idx = blockIdx.x * blockDim.x + threadIdx.x; idx < n1 + n2 + n3;
         idx += gridDim.x * blockDim.x) {
        int i = idx;
        if (i < n1)           pack_one(W1, g_Wtc1, i);
        else if (i < n1 + n2) pack_one(W2, g_Wtc2, i - n1);
        else                  pack_one(Wm, g_Wtcm, i - n1 - n2);
    }
}

// ---------------------------------------------------------------------------
// Fused aggregate + TF32 GEMM, GROWS=32, 8 warps.
// Phase 1: 4 nodes per warp (K=128) / 2x2 nodes (K=64); 8-wide gather MLP.
// Phase 2: warp = (rg = warp>>2: 16-row group, nq = warp&3: 32-col quarter),
//          acc[4][4] (16 regs). BN-stats epilogue via shfl + atomics.
// ---------------------------------------------------------------------------
template <int K, bool BN>
__global__ __launch_bounds__(256) void agg_gemm_tc_kernel(
        const float* __restrict__ H,
        const unsigned* __restrict__ Wtc,
        const float* __restrict__ b,
        const float* __restrict__ gamma,
        const float* __restrict__ beta,
        const float* __restrict__ statsIn,
        float* __restrict__ C,
        float* __restrict__ statsOut) {
    constexpr int KP = K + 4;
    __shared__ float xs[GROWS * KP];
    __shared__ float sc[CH], sh[CH];
    const int row0 = blockIdx.x * GROWS;
    const int tid = threadIdx.x;
    const int warp = tid >> 5;
    const int lane = tid & 31;

    if (BN) {
        if (tid < CH) {
            float mean = statsIn[tid] * (1.0f / NNODES);
            float var = statsIn[CH + tid] * (1.0f / NNODES) - mean * mean;
            float scale = gamma[tid] * rsqrtf(var + 1e-5f);
            sc[tid] = scale;
            sh[tid] = beta[tid] - mean * scale;
        }
        __syncthreads();
    }

    // ---------------- Phase 1: gather-aggregate into xs ----------------
    const int RPW = (K == 128) ? 1 : 2;
    const int l16 = (K == 128) ? lane : (lane & 15);
    const int half = (K == 128) ? 0 : (lane >> 4);
    const float4* h4 = (const float4*)H;
    const int rowlen = K / 4;
    float4 scv = make_float4(0, 0, 0, 0), shv = scv;
    if (BN) {
        scv = *(const float4*)&sc[l16 * 4];
        shv = *(const float4*)&sh[l16 * 4];
    }

#pragma unroll 1
    for (int i = 0; i < 4 / RPW; i++) {
        int node = min(row0 + warp * 4 + RPW * i + half, NNODES - 1);
        float di = g_dinv[node];
        float s = di * di;
        float4 hv = h4[(size_t)node * rowlen + l16];
        float4 acc;
        if (BN) {
            acc.x = s * fmaxf(hv.x * scv.x + shv.x, 0.0f);
            acc.y = s * fmaxf(hv.y * scv.y + shv.y, 0.0f);
            acc.z = s * fmaxf(hv.z * scv.z + shv.z, 0.0f);
            acc.w = s * fmaxf(hv.w * scv.w + shv.w, 0.0f);
        } else {
            acc = make_float4(s * hv.x, s * hv.y, s * hv.z, s * hv.w);
        }
        int j = g_rowptr[node];
        int end = g_rowptr[node + 1];
        for (; j + 7 < end; j += 8) {
            int si[8];
            float ni[8];
            float4 vi[8];
#pragma unroll
            for (int u = 0; u < 8; u++) csr_get(g_csr[j + u], si[u], ni[u]);
#pragma unroll
            for (int u = 0; u < 8; u++) vi[u] = h4[(size_t)si[u] * rowlen + l16];
#pragma unroll
            for (int u = 0; u < 8; u++) acc_edge<BN>(acc, vi[u], ni[u], scv, shv);
        }
        for (; j + 3 < end; j += 4) {
            int si[4];
            float ni[4];
            float4 vi[4];
#pragma unroll
            for (int u = 0; u < 4; u++) csr_get(g_csr[j + u], si[u], ni[u]);
#pragma unroll
            for (int u = 0; u < 4; u++) vi[u] = h4[(size_t)si[u] * rowlen + l16];
#pragma unroll
            for (int u = 0; u < 4; u++) acc_edge<BN>(acc, vi[u], ni[u], scv, shv);
        }
        for (; j < end; j++) {
            int s0;
            float n0;
            csr_get(g_csr[j], s0, n0);
            acc_edge<BN>(acc, h4[(size_t)s0 * rowlen + l16], n0, scv, shv);
        }
        *(float4*)&xs[(warp * 4 + RPW * i + half) * KP + l16 * 4] = acc;
    }
    __syncthreads();

    // ---------------- Phase 2: TF32 MMA (warp = rg x nq) ----------------
    const int rg = warp >> 2;          // 0..1 -> rows [16rg, 16rg+16)
    const int nq = warp & 3;           // 0..3 -> n-tiles [4nq, 4nq+4)
    const int r0 = lane >> 2;
    const int c0 = lane & 3;

    float acc[4][4];
#pragma unroll
    for (int nt = 0; nt < 4; nt++)
#pragma unroll
        for (int i = 0; i < 4; i++) acc[nt][i] = 0.0f;

    const float* a_lo = &xs[(16 * rg + r0) * KP];
    const float* a_hi = a_lo + 8 * KP;

#pragma unroll
    for (int kt = 0; kt < K / 8; kt++) {
        int col = kt * 8 + c0;
        unsigned a0 = cvt_tf32(a_lo[col]);
        unsigned a1 = cvt_tf32(a_hi[col]);
        unsigned a2 = cvt_tf32(a_lo[col + 4]);
        unsigned a3 = cvt_tf32(a_hi[col + 4]);
        const uint2* wrow = (const uint2*)(Wtc + (size_t)(kt * 16 + nq * 4) * 64) + lane;
#pragma unroll
        for (int nt = 0; nt < 4; nt++) {
            uint2 bw = wrow[nt * 32];
            mma_tf32(acc[nt], a0, a1, a2, a3, bw.x, bw.y);
        }
    }

    const int ra = row0 + 16 * rg + r0;
    const int rb = ra + 8;
    const bool va = ra < NNODES, vb = rb < NNODES;
#pragma unroll
    for (int nt = 0; nt < 4; nt++) {
        int c = nq * 32 + nt * 8 + c0 * 2;
        float b0 = b[c], b1 = b[c + 1];
        float v00 = acc[nt][0] + b0, v01 = acc[nt][1] + b1;
        float v10 = acc[nt][2] + b0, v11 = acc[nt][3] + b1;
        if (va) {
            C[(size_t)ra * CH + c] = v00;
            C[(size_t)ra * CH + c + 1] = v01;
        }
        if (vb) {
            C[(size_t)rb * CH + c] = v10;
            C[(size_t)rb * CH + c + 1] = v11;
        }
        float s0 = (va ? v00 : 0.0f) + (vb ? v10 : 0.0f);
        float q0 = (va ? v00 * v00 : 0.0f) + (vb ? v10 * v10 : 0.0f);
        float s1 = (va ? v01 : 0.0f) + (vb ? v11 : 0.0f);
        float q1 = (va ? v01 * v01 : 0.0f) + (vb ? v11 * v11 : 0.0f);
#pragma unroll
        for (int m = 16; m >= 4; m >>= 1) {
            s0 += __shfl_xor_sync(0xFFFFFFFF, s0, m);
            q0 += __shfl_xor_sync(0xFFFFFFFF, q0, m);
            s1 += __shfl_xor_sync(0xFFFFFFFF, s1, m);
            q1 += __shfl_xor_sync(0xFFFFFFFF, q1, m);
        }
        if (r0 == 0) {
            atomicAdd(&statsOut[c], s0);
            atomicAdd(&statsOut[CH + c], q0);
            atomicAdd(&statsOut[c + 1], s1);
            atomicAdd(&statsOut[CH + c + 1], q1);
        }
    }
}

// ---------------------------------------------------------------------------
// Final fused layer, TF32 TC, 512 threads, 128 rows/block (dynamic smem).
// ---------------------------------------------------------------------------
__global__ __launch_bounds__(512) void final_tc_kernel(const float* __restrict__ h,
                                                       const float* __restrict__ dist,
                                                       const float* __restrict__ degf,
                                                       const float* __restrict__ Wd,
                                                       const float* __restrict__ bd,
                                                       const float* __restrict__ Wg,
                                                       const float* __restrict__ bg,
                                                       const unsigned* __restrict__ Wtc,
                                                       const float* __restrict__ bm,
                                                       const float* __restrict__ gamma,
                                                       const float* __restrict__ beta,
                                                       float* __restrict__ out) {
    extern __shared__ float smem[];
    float* cs = smem;                       // [GROWS_F][CSP]
    float* sc = smem + GROWS_F * CSP;
    float* sh = sc + CH;
    float* swd = sh + CH;
    float* sbd = swd + CH;
    float* swg = sbd + CH;
    float* sbg = swg + CH;
    const int row0 = blockIdx.x * GROWS_F;
    const int tid = threadIdx.x;

    if (tid < CH) {
        float mean = g_stats[2 * CH + tid] * (1.0f / NNODES);
        float var = g_stats[3 * CH + tid] * (1.0f / NNODES) - mean * mean;
        float scale = gamma[tid] * rsqrtf(var + 1e-5f);
        sc[tid] = scale;
        sh[tid] = beta[tid] - mean * scale;
        swd[tid] = Wd[tid];
        sbd[tid] = bd[tid];
        swg[tid] = Wg[tid];
        sbg[tid] = bg[tid];
    }
    __syncthreads();

    const float4* h4 = (const float4*)h;
#pragma unroll 1
    for (int i = tid; i < GROWS_F * CH / 4; i += 512) {
        int r = i >> 5;
        int cc = (i & 31) * 4;
        int row = min(row0 + r, NNODES - 1);
        float4 v = h4[(size_t)row * 32 + (i & 31)];
        float4 scv = *(const float4*)&sc[cc];
        float4 shv = *(const float4*)&sh[cc];
        v.x = fmaxf(v.x * scv.x + shv.x, 0.0f);
        v.y = fmaxf(v.y * scv.y + shv.y, 0.0f);
        v.z = fmaxf(v.z * scv.z + shv.z, 0.0f);
        v.w = fmaxf(v.w * scv.w + shv.w, 0.0f);
        *(float4*)&cs[r * CSP + cc] = v;
    }
    __syncthreads();

    const int warp = tid >> 5;
    const int lane = tid & 31;
    const int rg = warp >> 1;
    const int chf = warp & 1;
    const int r0 = lane >> 2;
    const int c0 = lane & 3;

    const int ra = row0 + 16 * rg + r0;
    const int rb = ra + 8;
    const float dra = dist[min(ra, NNODES - 1)];
    const float drb = dist[min(rb, NNODES - 1)];
    const float gra = degf[min(ra, NNODES - 1)];
    const float grb = degf[min(rb, NNODES - 1)];

    float acc[8][4];
#pragma unroll
    for (int nt = 0; nt < 8; nt++)
#pragma unroll
        for (int i = 0; i < 4; i++) acc[nt][i] = 0.0f;

    const float* a_lo = &cs[(16 * rg + r0) * CSP];
    const float* a_hi = a_lo + 8 * CSP;

#pragma unroll
    for (int kt = 0; kt < 16; kt++) {
        int col = kt * 8 + c0;
        unsigned a0 = cvt_tf32(a_lo[col]);
        unsigned a1 = cvt_tf32(a_hi[col]);
        unsigned a2 = cvt_tf32(a_lo[col + 4]);
        unsigned a3 = cvt_tf32(a_hi[col + 4]);
        const uint2* wrow = (const uint2*)(Wtc + (size_t)(kt * 16 + chf * 8) * 64) + lane;
#pragma unroll
        for (int nt = 0; nt < 8; nt++) {
            uint2 bw = wrow[nt * 32];
            mma_tf32(acc[nt], a0, a1, a2, a3, bw.x, bw.y);
        }
    }
#pragma unroll
    for (int kt = 16; kt < 32; kt++) {
        int kk = (kt - 16) * 8 + c0;
        unsigned a0 = cvt_tf32(fmaxf(dra * swd[kk] + sbd[kk], 0.0f));
        unsigned a1 = cvt_tf32(fmaxf(drb * swd[kk] + sbd[kk], 0.0f));
        unsigned a2 = cvt_tf32(fmaxf(dra * swd[kk + 4] + sbd[kk + 4], 0.0f));
        unsigned a3 = cvt_tf32(fmaxf(drb * swd[kk + 4] + sbd[kk + 4], 0.0f));
        const uint2* wrow = (const uint2*)(Wtc + (size_t)(kt * 16 + chf * 8) * 64) + lane;
#pragma unroll
        for (int nt = 0; nt < 8; nt++) {
            uint2 bw = wrow[nt * 32];
            mma_tf32(acc[nt], a0, a1, a2, a3, bw.x, bw.y);
        }
    }
#pragma unroll
    for (int kt = 32; kt < 48; kt++) {
        int kk = (kt - 32) * 8 + c0;
        unsigned a0 = cvt_tf32(fmaxf(gra * swg[kk] + sbg[kk], 0.0f));
        unsigned a1 = cvt_tf32(fmaxf(grb * swg[kk] + sbg[kk], 0.0f));
        unsigned a2 = cvt_tf32(fmaxf(gra * swg[kk + 4] + sbg[kk + 4], 0.0f));
        unsigned a3 = cvt_tf32(fmaxf(grb * swg[kk + 4] + sbg[kk + 4], 0.0f));
        const uint2* wrow = (const uint2*)(Wtc + (size_t)(kt * 16 + chf * 8) * 64) + lane;
#pragma unroll
        for (int nt = 0; nt < 8; nt++) {
            uint2 bw = wrow[nt * 32];
            mma_tf32(acc[nt], a0, a1, a2, a3, bw.x, bw.y);
        }
    }

#pragma unroll
    for (int nt = 0; nt < 8; nt++) {
        int c = chf * 64 + nt * 8 + c0 * 2;
        float bm0 = bm[c], bm1 = bm[c + 1];
        if (ra < NNODES) {
            out[(size_t)ra * CH + c] = acc[nt][0] + bm0;
            out[(size_t)ra * CH + c + 1] = acc[nt][1] + bm1;
        }
        if (rb < NNODES) {
            out[(size_t)rb * CH + c] = acc[nt][2] + bm0;
            out[(size_t)rb * CH + c + 1] = acc[nt][3] + bm1;
        }
    }
}

// ---------------------------------------------------------------------------
extern "C" void kernel_launch(void* const* d_in, const int* in_sizes, int n_in,
                              void* d_out, int out_size) {
    const float* x     = (const float*)d_in[0];
    const void*  ei    = d_in[1];
    const float* ew    = (const float*)d_in[2];
    const float* dist  = (const float*)d_in[3];
    const float* degf  = (const float*)d_in[4];
    const float* W1    = (const float*)d_in[5];
    const float* b1    = (const float*)d_in[6];
    const float* W2    = (const float*)d_in[7];
    const float* b2    = (const float*)d_in[8];
    const float* g1    = (const float*)d_in[9];
    const float* be1   = (const float*)d_in[10];
    const float* g2    = (const float*)d_in[11];
    const float* be2   = (const float*)d_in[12];
    const float* Wd    = (const float*)d_in[13];
    const float* bd    = (const float*)d_in[14];
    const float* Wg    = (const float*)d_in[15];
    const float* bg    = (const float*)d_in[16];
    const float* Wm    = (const float*)d_in[17];
    const float* bm    = (const float*)d_in[18];
    float* out = (float*)d_out;

    float *bufA, *bufB, *stats;
    unsigned *Wtc1, *Wtc2, *Wtcm;
    cudaGetSymbolAddress((void**)&bufA, g_bufA);
    cudaGetSymbolAddress((void**)&bufB, g_bufB);
    cudaGetSymbolAddress((void**)&stats, g_stats);
    cudaGetSymbolAddress((void**)&Wtc1, g_Wtc1);
    cudaGetSymbolAddress((void**)&Wtc2, g_Wtc2);
    cudaGetSymbolAddress((void**)&Wtcm, g_Wtcm);

    const int nodeBlocks = (NNODES + 255) / 256;
    const int edgeBlocks = (NEDGES + 255) / 256;
    const int gemmBlocks = (NNODES + GROWS - 1) / GROWS;       // 3125
    const int finBlocks  = (NNODES + GROWS_F - 1) / GROWS_F;   // 782
    const int FIN_SMEM = (GROWS_F * CSP + 6 * CH) * 4;         // 70656 B

    cudaFuncSetAttribute(final_tc_kernel, cudaFuncAttributeMaxDynamicSharedMemorySize, FIN_SMEM);

    // --- gcn_norm + CSR build + packing ---
    detect_idx_kernel<<<1, 256>>>((const int*)ei);
    deg_init_kernel<<<nodeBlocks, 256>>>();
    pack_kernel<<<160, 256>>>(W1, W2, Wm);
    deg_count_kernel<<<edgeBlocks, 256>>>(ei, ew);
    scanA_kernel<<<SCAN_BLOCKS, SCAN_BT>>>();
    scanB_kernel<<<1, 256>>>();
    scanC_kernel<<<SCAN_BLOCKS, SCAN_BT>>>();
    fill_kernel<<<edgeBlocks, 256>>>(ei, ew);

    // --- layer 1: fused aggregate(x) + GEMM (stats1) ---
    agg_gemm_tc_kernel<CIN, false><<<gemmBlocks, 256>>>(
        x, Wtc1, b1, nullptr, nullptr, nullptr, bufB, stats);

    // --- layer 2: fused aggregate(bn1(h1)) + GEMM (stats2) ---
    agg_gemm_tc_kernel<CH, true><<<gemmBlocks, 256>>>(
        bufB, Wtc2, b2, g1, be1, stats, bufA, stats + 2 * CH);

    // --- final (TF32 TC, 512 threads, 128 rows/block) ---
    final_tc_kernel<<<finBlocks, 512, FIN_SMEM>>>(bufA, dist, degf, Wd, bd, Wg, bg,
                                                  Wtcm, bm, g2, be2, out);
}

// round 15
// speedup vs baseline: 1.1979x; 1.0107x over previous
#include <cuda_runtime.h>
#include <math.h>

// Problem-fixed dimensions
#define NNODES 100000
#define NEDGES 1600000
#define CIN 64
#define CH 128
#define GROWS 32         // rows per block in fused agg+GEMM kernels
#define GROWS_F 128      // rows per block in final kernel (512 threads)
#define KFIN 384
#define CSP 132          // padded smem row stride (128+4) -> conflict-free frags

// Scratch (__device__ globals; no allocation allowed)
__device__ __align__(128) float g_bufA[(size_t)NNODES * CH];
__device__ __align__(128) float g_bufB[(size_t)NNODES * CH];
__device__ __align__(128) float g_dinv[NNODES];
__device__ __align__(128) float g_stats[4 * CH];        // [sum1|sq1|sum2|sq2]
__device__ __align__(128) unsigned long long g_degcnt[NNODES]; // (cnt<<44)|fix32(w)
__device__ __align__(128) int   g_rowptr[NNODES + 1];
__device__ __align__(128) int   g_cursor[NNODES];
__device__ __align__(128) unsigned long long g_csr[NEDGES];  // (norm<<32)|src
__device__ __align__(128) unsigned g_Wtc1[CIN * CH];    // tf32 B-frag packed W1
__device__ __align__(128) unsigned g_Wtc2[CH * CH];     // tf32 B-frag packed W2
__device__ __align__(128) unsigned g_Wtcm[KFIN * CH];   // tf32 B-frag packed Wm
__device__ __align__(128) int   g_part[256];            // scan partials
__device__ int g_idx32;

#define SCAN_BLOCKS 196
#define SCAN_BT 512

// ---------------------------------------------------------------------------
typedef unsigned long long ull;

__device__ __forceinline__ void csr_get(ull e, int& src, float& norm) {
    src = (int)(unsigned)(e & 0xFFFFFFFFull);
    norm = __uint_as_float((unsigned)(e >> 32));
}
__device__ __forceinline__ unsigned cvt_tf32(float f) {
    unsigned u;
    asm("cvt.rna.tf32.f32 %0, %1;" : "=r"(u) : "f"(f));
    return u;
}
__device__ __forceinline__ void mma_tf32(float* d, unsigned a0, unsigned a1,
                                         unsigned a2, unsigned a3,
                                         unsigned b0, unsigned b1) {
    asm("mma.sync.aligned.m16n8k8.row.col.f32.tf32.tf32.f32 "
        "{%0,%1,%2,%3},{%4,%5,%6,%7},{%8,%9},{%0,%1,%2,%3};"
        : "+f"(d[0]), "+f"(d[1]), "+f"(d[2]), "+f"(d[3])
        : "r"(a0), "r"(a1), "r"(a2), "r"(a3), "r"(b0), "r"(b1));
}

template <bool BN>
__device__ __forceinline__ void acc_edge(float4& acc, float4 v, float n,
                                         const float4& scv, const float4& shv) {
    if (BN) {
        acc.x += n * fmaxf(v.x * scv.x + shv.x, 0.0f);
        acc.y += n * fmaxf(v.y * scv.y + shv.y, 0.0f);
        acc.z += n * fmaxf(v.z * scv.z + shv.z, 0.0f);
        acc.w += n * fmaxf(v.w * scv.w + shv.w, 0.0f);
    } else {
        acc.x += n * v.x;
        acc.y += n * v.y;
        acc.z += n * v.z;
        acc.w += n * v.w;
    }
}

// ---------------------------------------------------------------------------
__global__ void detect_idx_kernel(const int* __restrict__ ei) {
    __shared__ int s_any;
    if (threadIdx.x == 0) s_any = 0;
    __syncthreads();
    int any = 0;
    for (int i = 1 + 2 * threadIdx.x; i < 4096; i += 2 * blockDim.x) any |= ei[i];
    if (any) atomicOr(&s_any, 1);
    __syncthreads();
    if (threadIdx.x == 0) g_idx32 = (s_any != 0) ? 1 : 0;
}

__device__ __forceinline__ void load_edge(const void* ei, int e, int& src, int& dst) {
    if (g_idx32) {
        const int* p = (const int*)ei;
        src = p[e];
        dst = p[NEDGES + e];
    } else {
        const long long* p = (const long long*)ei;
        src = (int)p[e];
        dst = (int)p[NEDGES + e];
    }
}

__global__ void deg_init_kernel() {
    int i = blockIdx.x * blockDim.x + threadIdx.x;
    if (i < NNODES) g_degcnt[i] = 0ULL;
    if (i < 4 * CH) g_stats[i] = 0.0f;
}

// One packed atomic per edge: (count << 44) + fixed-point(w, 2^-32)
__global__ void deg_count_kernel(const void* __restrict__ ei,
                                 const float* __restrict__ ew) {
    int e = blockIdx.x * blockDim.x + threadIdx.x;
    if (e >= NEDGES) return;
    int dst;
    if (g_idx32) dst = ((const int*)ei)[NEDGES + e];
    else         dst = (int)((const long long*)ei)[NEDGES + e];
    ull v = (1ULL << 44) | (ull)(ew[e] * 4294967296.0f);
    atomicAdd(&g_degcnt[dst], v);
}

// ---------------------------------------------------------------------------
// 3-phase multi-block scan; scanA decodes degcnt -> counts + dinv.
// ---------------------------------------------------------------------------
__global__ __launch_bounds__(SCAN_BT) void scanA_kernel() {
    __shared__ int ssum[SCAN_BT];
    int i = blockIdx.x * SCAN_BT + threadIdx.x;
    int c = 0;
    if (i < NNODES) {
        ull v = g_degcnt[i];
        c = (int)(v >> 44);
        float deg = 1.0f + (float)(v & 0xFFFFFFFFFFFULL) * 2.3283064365386963e-10f;
        g_dinv[i] = rsqrtf(deg);
        g_cursor[i] = c;                 // raw count (used by scanC)
    }
    ssum[threadIdx.x] = c;
    __syncthreads();
    for (int off = 1; off < SCAN_BT; off <<= 1) {
        int v = (threadIdx.x >= off) ? ssum[threadIdx.x - off] : 0;
        __syncthreads();
        ssum[threadIdx.x] += v;
        __syncthreads();
    }
    if (i < NNODES) g_rowptr[i] = ssum[threadIdx.x];
    if (threadIdx.x == SCAN_BT - 1) g_part[blockIdx.x] = ssum[threadIdx.x];
}

__global__ __launch_bounds__(256) void scanB_kernel() {
    __shared__ int ssum[256];
    int t = threadIdx.x;
    ssum[t] = (t < SCAN_BLOCKS) ? g_part[t] : 0;
    __syncthreads();
    for (int off = 1; off < 256; off <<= 1) {
        int v = (t >= off) ? ssum[t - off] : 0;
        __syncthreads();
        ssum[t] += v;
        __syncthreads();
    }
    g_part[t] = (t == 0) ? 0 : ssum[t - 1];
    if (t == 255) g_rowptr[NNODES] = ssum[255];
}

__global__ __launch_bounds__(SCAN_BT) void scanC_kernel() {
    int i = blockIdx.x * SCAN_BT + threadIdx.x;
    if (i >= NNODES) return;
    int off = g_part[blockIdx.x];
    int excl = g_rowptr[i] + off - g_cursor[i];
    g_rowptr[i] = excl;
    g_cursor[i] = excl;
}

__global__ void fill_kernel(const void* __restrict__ ei,
                            const float* __restrict__ ew) {
    int e = blockIdx.x * blockDim.x + threadIdx.x;
    if (e >= NEDGES) return;
    int src, dst;
    load_edge(ei, e, src, dst);
    float norm = g_dinv[src] * ew[e] * g_dinv[dst];
    int pos = atomicAdd(&g_cursor[dst], 1);
    g_csr[pos] = ((ull)__float_as_uint(norm) << 32) | (unsigned)src;
}

// ---------------------------------------------------------------------------
// Pack weight matrices into tf32 B-fragment lane order.
// ---------------------------------------------------------------------------
__device__ __forceinline__ void pack_one(const float* W, unsigned* Wtc, int i) {
    int tile = i >> 6;              // kt*16 + nt
    int within = i & 63;
    int t = within >> 1;
    int e = within & 1;
    int kt = tile >> 4;
    int nt = tile & 15;
    int k = kt * 8 + (t & 3) + e * 4;
    int n = nt * 8 + (t >> 2);
    Wtc[i] = cvt_tf32(W[k * CH + n]);
}

__global__ void pack_kernel(const float* __restrict__ W1,
                            const float* __restrict__ W2,
                            const float* __restrict__ Wm) {
    const int n1 = CIN * CH;
    const int n2 = CH * CH;
    const int n3 = KFIN * CH;
    for (int idx = blockIdx.x * blockDim.x + threadIdx.x; idx < n1 + n2 + n3;
         idx += gridDim.x * blockDim.x) {
        int i = idx;
        if (i < n1)           pack_one(W1, g_Wtc1, i);
        else if (i < n1 + n2) pack_one(W2, g_Wtc2, i - n1);
        else                  pack_one(Wm, g_Wtcm, i - n1 - n2);
    }
}

// ---------------------------------------------------------------------------
// Fused aggregate + TF32 GEMM, GROWS=32, 8 warps.
// Phase 1 (lane owns 8 channels = 2 float4):
//   K=128: half-warp (16 lanes) per node -> 2-node serial chain per half-warp
//   K=64:  8 lanes per node -> all 4 nodes concurrent (chain length 1)
// Phase 2: warp = (rg = warp>>2, nq = warp&3), acc[4][4].
// ---------------------------------------------------------------------------
template <int K, bool BN>
__global__ __launch_bounds__(256) void agg_gemm_tc_kernel(
        const float* __restrict__ H,
        const unsigned* __restrict__ Wtc,
        const float* __restrict__ b,
        const float* __restrict__ gamma,
        const float* __restrict__ beta,
        const float* __restrict__ statsIn,
        float* __restrict__ C,
        float* __restrict__ statsOut) {
    constexpr int KP = K + 4;
    __shared__ float xs[GROWS * KP];
    __shared__ float sc[CH], sh[CH];
    const int row0 = blockIdx.x * GROWS;
    const int tid = threadIdx.x;
    const int warp = tid >> 5;
    const int lane = tid & 31;

    if (BN) {
        if (tid < CH) {
            float mean = statsIn[tid] * (1.0f / NNODES);
            float var = statsIn[CH + tid] * (1.0f / NNODES) - mean * mean;
            float scale = gamma[tid] * rsqrtf(var + 1e-5f);
            sc[tid] = scale;
            sh[tid] = beta[tid] - mean * scale;
        }
        __syncthreads();
    }

    // ---------------- Phase 1: gather-aggregate into xs ----------------
    {
        const int LPN = (K == 128) ? 16 : 8;     // lanes per node
        const int sub = lane / LPN;              // node index within warp group
        const int ll = lane % LPN;               // lane within node (owns 8 ch)
        const int CHAIN = (K == 128) ? 2 : 1;    // serial nodes per lane-group
        const int rowlen = K / 4;                // float4 per row
        const float4* h4 = (const float4*)H;
        const int cbase = ll * 8;                // first channel owned

        float4 scv0, shv0, scv1, shv1;
        if (BN) {
            scv0 = *(const float4*)&sc[cbase];
            shv0 = *(const float4*)&sh[cbase];
            scv1 = *(const float4*)&sc[cbase + 4];
            shv1 = *(const float4*)&sh[cbase + 4];
        } else {
            scv0 = shv0 = scv1 = shv1 = make_float4(0, 0, 0, 0);
        }

#pragma unroll 1
        for (int i = 0; i < CHAIN; i++) {
            int ridx = warp * 4 + sub * CHAIN + i;
            int node = min(row0 + ridx, NNODES - 1);
            float di = g_dinv[node];
            float s = di * di;
            size_t base = (size_t)node * rowlen + ll * 2;
            float4 h0 = h4[base], h1 = h4[base + 1];
            float4 acc0, acc1;
            if (BN) {
                acc0.x = s * fmaxf(h0.x * scv0.x + shv0.x, 0.0f);
                acc0.y = s * fmaxf(h0.y * scv0.y + shv0.y, 0.0f);
                acc0.z = s * fmaxf(h0.z * scv0.z + shv0.z, 0.0f);
                acc0.w = s * fmaxf(h0.w * scv0.w + shv0.w, 0.0f);
                acc1.x = s * fmaxf(h1.x * scv1.x + shv1.x, 0.0f);
                acc1.y = s * fmaxf(h1.y * scv1.y + shv1.y, 0.0f);
                acc1.z = s * fmaxf(h1.z * scv1.z + shv1.z, 0.0f);
                acc1.w = s * fmaxf(h1.w * scv1.w + shv1.w, 0.0f);
            } else {
                acc0 = make_float4(s * h0.x, s * h0.y, s * h0.z, s * h0.w);
                acc1 = make_float4(s * h1.x, s * h1.y, s * h1.z, s * h1.w);
            }
            int j = g_rowptr[node];
            int end = g_rowptr[node + 1];
            for (; j + 3 < end; j += 4) {
                int si[4];
                float ni[4];
                float4 v0[4], v1[4];
#pragma unroll
                for (int u = 0; u < 4; u++) csr_get(g_csr[j + u], si[u], ni[u]);
#pragma unroll
                for (int u = 0; u < 4; u++) {
                    size_t sb = (size_t)si[u] * rowlen + ll * 2;
                    v0[u] = h4[sb];
                    v1[u] = h4[sb + 1];
                }
#pragma unroll
                for (int u = 0; u < 4; u++) {
                    acc_edge<BN>(acc0, v0[u], ni[u], scv0, shv0);
                    acc_edge<BN>(acc1, v1[u], ni[u], scv1, shv1);
                }
            }
            for (; j < end; j++) {
                int s0;
                float n0;
                csr_get(g_csr[j], s0, n0);
                size_t sb = (size_t)s0 * rowlen + ll * 2;
                acc_edge<BN>(acc0, h4[sb], n0, scv0, shv0);
                acc_edge<BN>(acc1, h4[sb + 1], n0, scv1, shv1);
            }
            *(float4*)&xs[ridx * KP + cbase] = acc0;
            *(float4*)&xs[ridx * KP + cbase + 4] = acc1;
        }
    }
    __syncthreads();

    // ---------------- Phase 2: TF32 MMA (warp = rg x nq) ----------------
    const int rg = warp >> 2;          // 0..1 -> rows [16rg, 16rg+16)
    const int nq = warp & 3;           // 0..3 -> n-tiles [4nq, 4nq+4)
    const int r0 = lane >> 2;
    const int c0 = lane & 3;

    float acc[4][4];
#pragma unroll
    for (int nt = 0; nt < 4; nt++)
#pragma unroll
        for (int i = 0; i < 4; i++) acc[nt][i] = 0.0f;

    const float* a_lo = &xs[(16 * rg + r0) * KP];
    const float* a_hi = a_lo + 8 * KP;

#pragma unroll
    for (int kt = 0; kt < K / 8; kt++) {
        int col = kt * 8 + c0;
        unsigned a0 = cvt_tf32(a_lo[col]);
        unsigned a1 = cvt_tf32(a_hi[col]);
        unsigned a2 = cvt_tf32(a_lo[col + 4]);
        unsigned a3 = cvt_tf32(a_hi[col + 4]);
        const uint2* wrow = (const uint2*)(Wtc + (size_t)(kt * 16 + nq * 4) * 64) + lane;
#pragma unroll
        for (int nt = 0; nt < 4; nt++) {
            uint2 bw = wrow[nt * 32];
            mma_tf32(acc[nt], a0, a1, a2, a3, bw.x, bw.y);
        }
    }

    const int ra = row0 + 16 * rg + r0;
    const int rb = ra + 8;
    const bool va = ra < NNODES, vb = rb < NNODES;
#pragma unroll
    for (int nt = 0; nt < 4; nt++) {
        int c = nq * 32 + nt * 8 + c0 * 2;
        float b0 = b[c], b1 = b[c + 1];
        float v00 = acc[nt][0] + b0, v01 = acc[nt][1] + b1;
        float v10 = acc[nt][2] + b0, v11 = acc[nt][3] + b1;
        if (va) {
            C[(size_t)ra * CH + c] = v00;
            C[(size_t)ra * CH + c + 1] = v01;
        }
        if (vb) {
            C[(size_t)rb * CH + c] = v10;
            C[(size_t)rb * CH + c + 1] = v11;
        }
        float s0 = (va ? v00 : 0.0f) + (vb ? v10 : 0.0f);
        float q0 = (va ? v00 * v00 : 0.0f) + (vb ? v10 * v10 : 0.0f);
        float s1 = (va ? v01 : 0.0f) + (vb ? v11 : 0.0f);
        float q1 = (va ? v01 * v01 : 0.0f) + (vb ? v11 * v11 : 0.0f);
#pragma unroll
        for (int m = 16; m >= 4; m >>= 1) {
            s0 += __shfl_xor_sync(0xFFFFFFFF, s0, m);
            q0 += __shfl_xor_sync(0xFFFFFFFF, q0, m);
            s1 += __shfl_xor_sync(0xFFFFFFFF, s1, m);
            q1 += __shfl_xor_sync(0xFFFFFFFF, q1, m);
        }
        if (r0 == 0) {
            atomicAdd(&statsOut[c], s0);
            atomicAdd(&statsOut[CH + c], q0);
            atomicAdd(&statsOut[c + 1], s1);
            atomicAdd(&statsOut[CH + c + 1], q1);
        }
    }
}

// ---------------------------------------------------------------------------
// Final fused layer, TF32 TC, 512 threads, 128 rows/block (dynamic smem).
// ---------------------------------------------------------------------------
__global__ __launch_bounds__(512) void final_tc_kernel(const float* __restrict__ h,
                                                       const float* __restrict__ dist,
                                                       const float* __restrict__ degf,
                                                       const float* __restrict__ Wd,
                                                       const float* __restrict__ bd,
                                                       const float* __restrict__ Wg,
                                                       const float* __restrict__ bg,
                                                       const unsigned* __restrict__ Wtc,
                                                       const float* __restrict__ bm,
                                                       const float* __restrict__ gamma,
                                                       const float* __restrict__ beta,
                                                       float* __restrict__ out) {
    extern __shared__ float smem[];
    float* cs = smem;                       // [GROWS_F][CSP]
    float* sc = smem + GROWS_F * CSP;
    float* sh = sc + CH;
    float* swd = sh + CH;
    float* sbd = swd + CH;
    float* swg = sbd + CH;
    float* sbg = swg + CH;
    const int row0 = blockIdx.x * GROWS_F;
    const int tid = threadIdx.x;

    if (tid < CH) {
        float mean = g_stats[2 * CH + tid] * (1.0f / NNODES);
        float var = g_stats[3 * CH + tid] * (1.0f / NNODES) - mean * mean;
        float scale = gamma[tid] * rsqrtf(var + 1e-5f);
        sc[tid] = scale;
        sh[tid] = beta[tid] - mean * scale;
        swd[tid] = Wd[tid];
        sbd[tid] = bd[tid];
        swg[tid] = Wg[tid];
        sbg[tid] = bg[tid];
    }
    __syncthreads();

    const float4* h4 = (const float4*)h;
#pragma unroll 1
    for (int i = tid; i < GROWS_F * CH / 4; i += 512) {
        int r = i >> 5;
        int cc = (i & 31) * 4;
        int row = min(row0 + r, NNODES - 1);
        float4 v = h4[(size_t)row * 32 + (i & 31)];
        float4 scv = *(const float4*)&sc[cc];
        float4 shv = *(const float4*)&sh[cc];
        v.x = fmaxf(v.x * scv.x + shv.x, 0.0f);
        v.y = fmaxf(v.y * scv.y + shv.y, 0.0f);
        v.z = fmaxf(v.z * scv.z + shv.z, 0.0f);
        v.w = fmaxf(v.w * scv.w + shv.w, 0.0f);
        *(float4*)&cs[r * CSP + cc] = v;
    }
    __syncthreads();

    const int warp = tid >> 5;
    const int lane = tid & 31;
    const int rg = warp >> 1;
    const int chf = warp & 1;
    const int r0 = lane >> 2;
    const int c0 = lane & 3;

    const int ra = row0 + 16 * rg + r0;
    const int rb = ra + 8;
    const float dra = dist[min(ra, NNODES - 1)];
    const float drb = dist[min(rb, NNODES - 1)];
    const float gra = degf[min(ra, NNODES - 1)];
    const float grb = degf[min(rb, NNODES - 1)];

    float acc[8][4];
#pragma unroll
    for (int nt = 0; nt < 8; nt++)
#pragma unroll
        for (int i = 0; i < 4; i++) acc[nt][i] = 0.0f;

    const float* a_lo = &cs[(16 * rg + r0) * CSP];
    const float* a_hi = a_lo + 8 * CSP;

#pragma unroll
    for (int kt = 0; kt < 16; kt++) {
        int col = kt * 8 + c0;
        unsigned a0 = cvt_tf32(a_lo[col]);
        unsigned a1 = cvt_tf32(a_hi[col]);
        unsigned a2 = cvt_tf32(a_lo[col + 4]);
        unsigned a3 = cvt_tf32(a_hi[col + 4]);
        const uint2* wrow = (const uint2*)(Wtc + (size_t)(kt * 16 + chf * 8) * 64) + lane;
#pragma unroll
        for (int nt = 0; nt < 8; nt++) {
            uint2 bw = wrow[nt * 32];
            mma_tf32(acc[nt], a0, a1, a2, a3, bw.x, bw.y);
        }
    }
#pragma unroll
    for (int kt = 16; kt < 32; kt++) {
        int kk = (kt - 16) * 8 + c0;
        unsigned a0 = cvt_tf32(fmaxf(dra * swd[kk] + sbd[kk], 0.0f));
        unsigned a1 = cvt_tf32(fmaxf(drb * swd[kk] + sbd[kk], 0.0f));
        unsigned a2 = cvt_tf32(fmaxf(dra * swd[kk + 4] + sbd[kk + 4], 0.0f));
        unsigned a3 = cvt_tf32(fmaxf(drb * swd[kk + 4] + sbd[kk + 4], 0.0f));
        const uint2* wrow = (const uint2*)(Wtc + (size_t)(kt * 16 + chf * 8) * 64) + lane;
#pragma unroll
        for (int nt = 0; nt < 8; nt++) {
            uint2 bw = wrow[nt * 32];
            mma_tf32(acc[nt], a0, a1, a2, a3, bw.x, bw.y);
        }
    }
#pragma unroll
    for (int kt = 32; kt < 48; kt++) {
        int kk = (kt - 32) * 8 + c0;
        unsigned a0 = cvt_tf32(fmaxf(gra * swg[kk] + sbg[kk], 0.0f));
        unsigned a1 = cvt_tf32(fmaxf(grb * swg[kk] + sbg[kk], 0.0f));
        unsigned a2 = cvt_tf32(fmaxf(gra * swg[kk + 4] + sbg[kk + 4], 0.0f));
        unsigned a3 = cvt_tf32(fmaxf(grb * swg[kk + 4] + sbg[kk + 4], 0.0f));
        const uint2* wrow = (const uint2*)(Wtc + (size_t)(kt * 16 + chf * 8) * 64) + lane;
#pragma unroll
        for (int nt = 0; nt < 8; nt++) {
            uint2 bw = wrow[nt * 32];
            mma_tf32(acc[nt], a0, a1, a2, a3, bw.x, bw.y);
        }
    }

#pragma unroll
    for (int nt = 0; nt < 8; nt++) {
        int c = chf * 64 + nt * 8 + c0 * 2;
        float bm0 = bm[c], bm1 = bm[c + 1];
        if (ra < NNODES) {
            out[(size_t)ra * CH + c] = acc[nt][0] + bm0;
            out[(size_t)ra * CH + c + 1] = acc[nt][1] + bm1;
        }
        if (rb < NNODES) {
            out[(size_t)rb * CH + c] = acc[nt][2] + bm0;
            out[(size_t)rb * CH + c + 1] = acc[nt][3] + bm1;
        }
    }
}

// ---------------------------------------------------------------------------
extern "C" void kernel_launch(void* const* d_in, const int* in_sizes, int n_in,
                              void* d_out, int out_size) {
    const float* x     = (const float*)d_in[0];
    const void*  ei    = d_in[1];
    const float* ew    = (const float*)d_in[2];
    const float* dist  = (const float*)d_in[3];
    const float* degf  = (const float*)d_in[4];
    const float* W1    = (const float*)d_in[5];
    const float* b1    = (const float*)d_in[6];
    const float* W2    = (const float*)d_in[7];
    const float* b2    = (const float*)d_in[8];
    const float* g1    = (const float*)d_in[9];
    const float* be1   = (const float*)d_in[10];
    const float* g2    = (const float*)d_in[11];
    const float* be2   = (const float*)d_in[12];
    const float* Wd    = (const float*)d_in[13];
    const float* bd    = (const float*)d_in[14];
    const float* Wg    = (const float*)d_in[15];
    const float* bg    = (const float*)d_in[16];
    const float* Wm    = (const float*)d_in[17];
    const float* bm    = (const float*)d_in[18];
    float* out = (float*)d_out;

    float *bufA, *bufB, *stats;
    unsigned *Wtc1, *Wtc2, *Wtcm;
    cudaGetSymbolAddress((void**)&bufA, g_bufA);
    cudaGetSymbolAddress((void**)&bufB, g_bufB);
    cudaGetSymbolAddress((void**)&stats, g_stats);
    cudaGetSymbolAddress((void**)&Wtc1, g_Wtc1);
    cudaGetSymbolAddress((void**)&Wtc2, g_Wtc2);
    cudaGetSymbolAddress((void**)&Wtcm, g_Wtcm);

    const int nodeBlocks = (NNODES + 255) / 256;
    const int edgeBlocks = (NEDGES + 255) / 256;
    const int gemmBlocks = (NNODES + GROWS - 1) / GROWS;       // 3125
    const int finBlocks  = (NNODES + GROWS_F - 1) / GROWS_F;   // 782
    const int FIN_SMEM = (GROWS_F * CSP + 6 * CH) * 4;         // 70656 B

    cudaFuncSetAttribute(final_tc_kernel, cudaFuncAttributeMaxDynamicSharedMemorySize, FIN_SMEM);

    // --- gcn_norm + CSR build + packing ---
    detect_idx_kernel<<<1, 256>>>((const int*)ei);
    deg_init_kernel<<<nodeBlocks, 256>>>();
    pack_kernel<<<160, 256>>>(W1, W2, Wm);
    deg_count_kernel<<<edgeBlocks, 256>>>(ei, ew);
    scanA_kernel<<<SCAN_BLOCKS, SCAN_BT>>>();
    scanB_kernel<<<1, 256>>>();
    scanC_kernel<<<SCAN_BLOCKS, SCAN_BT>>>();
    fill_kernel<<<edgeBlocks, 256>>>(ei, ew);

    // --- layer 1: fused aggregate(x) + GEMM (stats1) ---
    agg_gemm_tc_kernel<CIN, false><<<gemmBlocks, 256>>>(
        x, Wtc1, b1, nullptr, nullptr, nullptr, bufB, stats);

    // --- layer 2: fused aggregate(bn1(h1)) + GEMM (stats2) ---
    agg_gemm_tc_kernel<CH, true><<<gemmBlocks, 256>>>(
        bufB, Wtc2, b2, g1, be1, stats, bufA, stats + 2 * CH);

    // --- final (TF32 TC, 512 threads, 128 rows/block) ---
    final_tc_kernel<<<finBlocks, 512, FIN_SMEM>>>(bufA, dist, degf, Wd, bd, Wg, bg,
                                                  Wtcm, bm, g2, be2, out);
}